// round 1
// baseline (speedup 1.0000x reference)
#include <cuda_runtime.h>
#include <cuda_bf16.h>

#define VOCAB 30000
#define EMB 128
#define ENC 128
#define BS 256
#define NNODES 1023

// Precomputed P[t][o] = dot(emb[t,:], W_c[o,:]) + b_c[o]   (15.36 MB scratch)
__device__ float g_P[VOCAB * ENC];

// ---------------------------------------------------------------------------
// Packed f32x2 FMA (Blackwell FFMA2) — 2x fp32 FMA throughput, PTX-only path.
// ---------------------------------------------------------------------------
__device__ __forceinline__ unsigned long long fma2(unsigned long long a,
                                                   unsigned long long b,
                                                   unsigned long long c) {
    unsigned long long d;
    asm("fma.rn.f32x2 %0, %1, %2, %3;" : "=l"(d) : "l"(a), "l"(b), "l"(c));
    return d;
}

// ---------------------------------------------------------------------------
// Kernel A: P = emb @ W_c^T + b_c
//   CTA: 128 threads, 32 emb rows x 128 out cols.
//   smem: W transposed [k][o] with stride 132 (pad kills STS/LDS conflicts),
//         A rows pre-packed as {a,a} f32x2 for broadcast LDS.64.
//   Thread (rg=tid>>5, cg=tid&31): 8 rows x 4 cols accumulated as 16 f32x2.
// ---------------------------------------------------------------------------
#define A_ROWS 32
#define W_STRIDE 132

__global__ void __launch_bounds__(128) pmat_kernel(const float* __restrict__ emb,
                                                   const float* __restrict__ Wc,
                                                   const float* __restrict__ bc) {
    extern __shared__ char smem_raw[];
    float* sW = (float*)smem_raw;                                    // 128*132*4 = 67584 B
    unsigned long long* sA = (unsigned long long*)(smem_raw + 128 * W_STRIDE * 4); // 32*128*8 = 32768 B

    const int tid = threadIdx.x;
    const int row0 = blockIdx.x * A_ROWS;

    // Load W transposed: sW[k*132 + o] = Wc[o*128 + k]. Reads coalesced.
    #pragma unroll 4
    for (int i = tid; i < 128 * 128; i += 128) {
        int o = i >> 7, k = i & 127;
        sW[k * W_STRIDE + o] = Wc[i];
    }
    // Load A tile, pre-packed as (a,a) f32x2. Zero-fill past VOCAB.
    #pragma unroll 4
    for (int i = tid; i < A_ROWS * 128; i += 128) {
        int r = i >> 7;
        float a = 0.0f;
        if (row0 + r < VOCAB) a = emb[(size_t)row0 * 128 + i];
        unsigned au = __float_as_uint(a);
        sA[i] = ((unsigned long long)au << 32) | (unsigned long long)au;
    }
    __syncthreads();

    const int rg = tid >> 5;   // row group: rows rg*8 .. rg*8+7
    const int cg = tid & 31;   // col group: cols cg*4 .. cg*4+3

    unsigned long long acc[8][2];
    #pragma unroll
    for (int r = 0; r < 8; r++) { acc[r][0] = 0ull; acc[r][1] = 0ull; }

    const unsigned long long* Arow = sA + (rg * 8) * 128;
    const float* Wcol = sW + cg * 4;

    #pragma unroll 8
    for (int k = 0; k < 128; k++) {
        // two f32x2 W operands via one LDS.128 (adjacent floats = packed lo/hi)
        ulonglong2 w = *(const ulonglong2*)(Wcol + k * W_STRIDE);
        #pragma unroll
        for (int r = 0; r < 8; r++) {
            unsigned long long aa = Arow[r * 128 + k];  // LDS.64 broadcast
            acc[r][0] = fma2(aa, w.x, acc[r][0]);
            acc[r][1] = fma2(aa, w.y, acc[r][1]);
        }
    }

    float4 bv = *(const float4*)(bc + cg * 4);
    #pragma unroll
    for (int r = 0; r < 8; r++) {
        int row = row0 + rg * 8 + r;
        if (row < VOCAB) {
            float x0, x1, x2, x3;
            asm("mov.b64 {%0,%1}, %2;" : "=f"(x0), "=f"(x1) : "l"(acc[r][0]));
            asm("mov.b64 {%0,%1}, %2;" : "=f"(x2), "=f"(x3) : "l"(acc[r][1]));
            float4 o;
            o.x = x0 + bv.x; o.y = x1 + bv.y; o.z = x2 + bv.z; o.w = x3 + bv.w;
            *(float4*)(g_P + (size_t)row * 128 + cg * 4) = o;
        }
    }
}

// ---------------------------------------------------------------------------
// Kernel B: per batch, bottom-up subtree sums over gathered P rows + max.
//   CTA = 1 batch, 512 threads: ch = tid&127 (coalesced 128B gathers/warp),
//   grp = tid>>7 picks nodes. Levels 9..6 fused: each level-6 subtree = 15
//   independent gathers (high MLP), sums + maxes in registers.
//   Levels 5..0 via smem ping-pong (bufA 32KB / bufB 16KB = 48KB static).
// ---------------------------------------------------------------------------
__shared__ float s_bufA[64 * 128];  // placed at file scope? no — must be in-kernel
// (note: actual shared arrays declared inside the kernel below)

__global__ void __launch_bounds__(512) tree_kernel(const int* __restrict__ tokens,
                                                   float* __restrict__ out) {
    __shared__ float bufA[64 * 128];   // 32768 B
    __shared__ float bufB[32 * 128];   // 16384 B  -> 48KB total

    const int b   = blockIdx.x;
    const int tid = threadIdx.x;
    const int ch  = tid & 127;
    const int grp = tid >> 7;
    const int* tokrow = tokens + (size_t)b * NNODES;

    float maxv = -3.4e38f;

    // ---- fused levels 9..6: 64 subtrees rooted at level-6 nodes q = 63+m ----
    for (int m = grp; m < 64; m += 4) {
        int q = 63 + m;
        float v[15];
        v[0] = g_P[(size_t)__ldg(&tokrow[q]) * 128 + ch];
        int b2 = 2 * q + 1, b4 = 4 * q + 3, b8 = 8 * q + 7;
        #pragma unroll
        for (int j = 0; j < 2; j++) v[1 + j] = g_P[(size_t)__ldg(&tokrow[b2 + j]) * 128 + ch];
        #pragma unroll
        for (int j = 0; j < 4; j++) v[3 + j] = g_P[(size_t)__ldg(&tokrow[b4 + j]) * 128 + ch];
        #pragma unroll
        for (int j = 0; j < 8; j++) v[7 + j] = g_P[(size_t)__ldg(&tokrow[b8 + j]) * 128 + ch];

        float s8[4];
        #pragma unroll
        for (int j = 0; j < 4; j++) {
            float lft = v[7 + 2 * j], rgt = v[8 + 2 * j];
            maxv = fmaxf(maxv, fmaxf(lft, rgt));            // leaves
            s8[j] = v[3 + j] + lft + rgt;                   // level-8 subtree sums
            maxv = fmaxf(maxv, s8[j]);
        }
        float s70 = v[1] + s8[0] + s8[1];
        float s71 = v[2] + s8[2] + s8[3];
        maxv = fmaxf(maxv, fmaxf(s70, s71));                // level-7
        float s6 = v[0] + s70 + s71;                        // level-6
        maxv = fmaxf(maxv, s6);
        bufA[m * 128 + ch] = s6;
    }
    __syncthreads();

    // ---- levels 5..0 via ping-pong ----
    // level l: cnt = 2^l nodes, node index base = 2^l - 1
    {
        // l5: A(64) -> B(32)
        for (int i = grp; i < 32; i += 4) {
            float v = bufA[(2 * i) * 128 + ch] + bufA[(2 * i + 1) * 128 + ch]
                    + g_P[(size_t)__ldg(&tokrow[31 + i]) * 128 + ch];
            maxv = fmaxf(maxv, v);
            bufB[i * 128 + ch] = v;
        }
        __syncthreads();
        // l4: B(32) -> A(16)
        for (int i = grp; i < 16; i += 4) {
            float v = bufB[(2 * i) * 128 + ch] + bufB[(2 * i + 1) * 128 + ch]
                    + g_P[(size_t)__ldg(&tokrow[15 + i]) * 128 + ch];
            maxv = fmaxf(maxv, v);
            bufA[i * 128 + ch] = v;
        }
        __syncthreads();
        // l3: A(16) -> B(8)
        for (int i = grp; i < 8; i += 4) {
            float v = bufA[(2 * i) * 128 + ch] + bufA[(2 * i + 1) * 128 + ch]
                    + g_P[(size_t)__ldg(&tokrow[7 + i]) * 128 + ch];
            maxv = fmaxf(maxv, v);
            bufB[i * 128 + ch] = v;
        }
        __syncthreads();
        // l2: B(8) -> A(4)
        if (grp < 4) {
            int i = grp;
            float v = bufB[(2 * i) * 128 + ch] + bufB[(2 * i + 1) * 128 + ch]
                    + g_P[(size_t)__ldg(&tokrow[3 + i]) * 128 + ch];
            maxv = fmaxf(maxv, v);
            bufA[i * 128 + ch] = v;
        }
        __syncthreads();
        // l1: A(4) -> B(2)
        if (grp < 2) {
            int i = grp;
            float v = bufA[(2 * i) * 128 + ch] + bufA[(2 * i + 1) * 128 + ch]
                    + g_P[(size_t)__ldg(&tokrow[1 + i]) * 128 + ch];
            maxv = fmaxf(maxv, v);
            bufB[i * 128 + ch] = v;
        }
        __syncthreads();
        // l0: root
        if (grp == 0) {
            float v = bufB[0 * 128 + ch] + bufB[1 * 128 + ch]
                    + g_P[(size_t)__ldg(&tokrow[0]) * 128 + ch];
            maxv = fmaxf(maxv, v);
        }
    }

    // ---- cross-group max reduction (reuse bufA as 512-float scratch) ----
    float* red = bufA;
    red[tid] = maxv;
    __syncthreads();
    if (grp == 0) {
        float m = fmaxf(fmaxf(red[ch], red[128 + ch]),
                        fmaxf(red[256 + ch], red[384 + ch]));
        out[(size_t)b * 128 + ch] = m;
    }
}

// ---------------------------------------------------------------------------
// kernel_launch: inputs per metadata order:
//   d_in[0]=tokens(int32 256x1023), d_in[1]=emb(f32 30000x128),
//   d_in[2]=W_c(f32 128x128), d_in[3]=b_c(f32 128), d_in[4]=bs (unused)
// out: f32 256x128
// ---------------------------------------------------------------------------
extern "C" void kernel_launch(void* const* d_in, const int* in_sizes, int n_in,
                              void* d_out, int out_size) {
    const int*   tokens = (const int*)d_in[0];
    const float* emb    = (const float*)d_in[1];
    const float* Wc     = (const float*)d_in[2];
    const float* bc     = (const float*)d_in[3];
    float*       out    = (float*)d_out;

    const size_t smemA = (size_t)128 * W_STRIDE * 4 + (size_t)A_ROWS * 128 * 8; // 100352 B
    cudaFuncSetAttribute(pmat_kernel, cudaFuncAttributeMaxDynamicSharedMemorySize, (int)smemA);

    const int gridA = (VOCAB + A_ROWS - 1) / A_ROWS;  // 938
    pmat_kernel<<<gridA, 128, smemA>>>(emb, Wc, bc);
    tree_kernel<<<BS, 512>>>(tokens, out);
}